// round 1
// baseline (speedup 1.0000x reference)
#include <cuda_runtime.h>
#include <math.h>

// ---------------------------------------------------------------------------
// ConvSlimCapsule3D: conv3d (votes) + 3-iteration dynamic routing + squash
// Shapes: x(2,8,16,32,32,32) w(128,16,3,3,3) b(128) biases(8,16,1,1,1)
// out: (2,8,16,32,32,32) = 8388608 floats
// ---------------------------------------------------------------------------

// Votes scratch: [b][pos][in*128 + oc] = 2 * 32768 * 1024 floats (256 MB)
__device__ float g_votes[67108864];

// ---------------- Conv kernel -------------------------------------------
// Tile: TZ=4 x TY=8 x TX=16 = 512 positions per block, 256 threads,
// each thread computes 2 positions (x, x+8) for 16 output channels per chunk.
// SMEM: input tile [16][6][10][18] = 17280 floats (69.1KB)
//       weight chunk / staging union: 8704 floats (34.8KB)
#define INS_FLOATS 17280
#define WS_FLOATS  8704
#define SMEM_BYTES ((INS_FLOATS + WS_FLOATS) * 4)

__global__ __launch_bounds__(256, 2)
void conv_votes_kernel(const float* __restrict__ x,
                       const float* __restrict__ w,
                       const float* __restrict__ cb) {
    extern __shared__ float smem[];
    float* ins = smem;                 // input tile
    float* ws  = smem + INS_FLOATS;    // weight chunk (aliased with staging)
    float* st  = smem + INS_FLOATS;    // staging [512][17]

    const int n = blockIdx.y;          // sample = b*8 + i
    const int b = n >> 3;
    const int i = n & 7;
    const int tile = blockIdx.x;       // 64 tiles: 2(x) * 4(y) * 8(z)
    const int x0 = (tile & 1) * 16;
    const int y0 = ((tile >> 1) & 3) * 8;
    const int z0 = (tile >> 3) * 4;
    const int tid = threadIdx.x;

    // ---- load input tile (with halo, zero padded) ----
    const float* xn = x + (size_t)n * 524288;  // 16*32768
    for (int idx = tid; idx < INS_FLOATS; idx += 256) {
        int ic = idx / 1080;
        int r  = idx - ic * 1080;
        int zz = r / 180;  r -= zz * 180;
        int yy = r / 18;
        int xx = r - yy * 18;
        int gz = z0 + zz - 1, gy = y0 + yy - 1, gx = x0 + xx - 1;
        float v = 0.0f;
        if ((unsigned)gz < 32u && (unsigned)gy < 32u && (unsigned)gx < 32u)
            v = xn[ic * 32768 + gz * 1024 + gy * 32 + gx];
        ins[idx] = v;
    }

    const int lx = tid & 7;
    const int ly = (tid >> 3) & 7;
    const int lz = tid >> 6;
    const int ibase_sp = (lz * 10 + ly) * 18 + lx;

    // ---- 8 chunks of 16 output channels ----
    for (int chunk = 0; chunk < 8; ++chunk) {
        const int c0 = chunk << 4;
        __syncthreads();  // staging reads from previous chunk done
        for (int idx = tid; idx < 6912; idx += 256)
            ws[idx] = w[c0 * 432 + idx];    // ws[u*432 + ic*27 + t]
        __syncthreads();

        float acc[16][2];
#pragma unroll
        for (int u = 0; u < 16; ++u) {
            float bv = __ldg(&cb[c0 + u]);
            acc[u][0] = bv; acc[u][1] = bv;
        }

        for (int ic = 0; ic < 16; ++ic) {
            float a27[27], b27[27];
            const float* ib = ins + ic * 1080 + ibase_sp;
#pragma unroll
            for (int dz = 0; dz < 3; ++dz)
#pragma unroll
                for (int dy = 0; dy < 3; ++dy)
#pragma unroll
                    for (int dx = 0; dx < 3; ++dx) {
                        const int t = (dz * 3 + dy) * 3 + dx;
                        const int off = dz * 180 + dy * 18 + dx;
                        a27[t] = ib[off];
                        b27[t] = ib[off + 8];
                    }
            const float* wb = ws + ic * 27;
#pragma unroll
            for (int u = 0; u < 16; ++u) {
                const float* wu = wb + u * 432;
#pragma unroll
                for (int t = 0; t < 27; ++t) {
                    const float ww = wu[t];
                    acc[u][0] = fmaf(ww, a27[t], acc[u][0]);
                    acc[u][1] = fmaf(ww, b27[t], acc[u][1]);
                }
            }
        }

        // ---- transpose-stage and write votes[b][pos][i*128 + c0 + c] ----
        __syncthreads();  // everyone done reading ws
        const int lA = lz * 128 + ly * 16 + lx;
#pragma unroll
        for (int u = 0; u < 16; ++u) {
            st[lA * 17 + u]       = acc[u][0];
            st[(lA + 8) * 17 + u] = acc[u][1];
        }
        __syncthreads();
        for (int k = 0; k < 32; ++k) {
            const int flat = (k << 8) + tid;
            const int pl = flat >> 4;
            const int c  = flat & 15;
            const int pz = pl >> 7, py = (pl >> 4) & 7, px = pl & 15;
            const int gpos = (z0 + pz) * 1024 + (y0 + py) * 32 + (x0 + px);
            g_votes[(size_t)(b * 32768 + gpos) * 1024 + i * 128 + c0 + c] =
                st[pl * 17 + c];
        }
    }
}

// ---------------- Routing kernel -----------------------------------------
// One warp per (b, pos). lane = o*4 + g; lane holds atoms [g*4, g*4+4) of
// out-capsule o across all 8 input capsules (32 vote floats in registers).
// Atom reductions: shfl xor {1,2}. Out-dim softmax reductions: shfl xor {4,8,16}.
__global__ __launch_bounds__(256)
void routing_kernel(const float* __restrict__ biases,
                    float* __restrict__ out) {
    __shared__ float sf[8 * 132];  // float4[8 warps][33]

    const int tid  = threadIdx.x;
    const int wrp  = tid >> 5;
    const int lane = tid & 31;
    const int o = lane >> 2;
    const int g = lane & 3;
    const int blk = blockIdx.x;
    const int b = blk >> 12;                // 4096 blocks per batch
    const int posbase = (blk & 4095) << 3;  // 8 positions per block
    const int pos = posbase + wrp;

    const float4* vp =
        (const float4*)(g_votes + (size_t)(b * 32768 + pos) * 1024);

    float v[8][4];
    float vn[8];
#pragma unroll
    for (int in = 0; in < 8; ++in) {
        float4 t = vp[in * 32 + o * 4 + g];
        v[in][0] = t.x; v[in][1] = t.y; v[in][2] = t.z; v[in][3] = t.w;
        float s = t.x * t.x + t.y * t.y + t.z * t.z + t.w * t.w;
        s += __shfl_xor_sync(0xffffffffu, s, 1);
        s += __shfl_xor_sync(0xffffffffu, s, 2);
        vn[in] = sqrtf(s);
    }
    const float4 bs = ((const float4*)biases)[o * 4 + g];

    float logit[8];
#pragma unroll
    for (int in = 0; in < 8; ++in) logit[in] = 0.0f;

    float p0, p1, p2, p3;
    for (int it = 0; it < 3; ++it) {
        float route[8];
        if (it == 0) {
#pragma unroll
            for (int in = 0; in < 8; ++in) route[in] = 0.125f;
        } else {
#pragma unroll
            for (int in = 0; in < 8; ++in) {
                float m = logit[in];
                m = fmaxf(m, __shfl_xor_sync(0xffffffffu, m, 4));
                m = fmaxf(m, __shfl_xor_sync(0xffffffffu, m, 8));
                m = fmaxf(m, __shfl_xor_sync(0xffffffffu, m, 16));
                float e = expf(logit[in] - m);
                float s = e;
                s += __shfl_xor_sync(0xffffffffu, s, 4);
                s += __shfl_xor_sync(0xffffffffu, s, 8);
                s += __shfl_xor_sync(0xffffffffu, s, 16);
                route[in] = e / s;
            }
        }
        p0 = bs.x; p1 = bs.y; p2 = bs.z; p3 = bs.w;
#pragma unroll
        for (int in = 0; in < 8; ++in) {
            p0 = fmaf(route[in], v[in][0], p0);
            p1 = fmaf(route[in], v[in][1], p1);
            p2 = fmaf(route[in], v[in][2], p2);
            p3 = fmaf(route[in], v[in][3], p3);
        }
        if (it < 2) {
            float pn = p0 * p0 + p1 * p1 + p2 * p2 + p3 * p3;
            pn += __shfl_xor_sync(0xffffffffu, pn, 1);
            pn += __shfl_xor_sync(0xffffffffu, pn, 2);
            pn = sqrtf(pn);
#pragma unroll
            for (int in = 0; in < 8; ++in) {
                float d = p0 * v[in][0] + p1 * v[in][1] +
                          p2 * v[in][2] + p3 * v[in][3];
                d += __shfl_xor_sync(0xffffffffu, d, 1);
                d += __shfl_xor_sync(0xffffffffu, d, 2);
                logit[in] += d / fmaxf(pn * vn[in], 1e-8f);
            }
        }
    }

    // squash over atoms
    float nsq = p0 * p0 + p1 * p1 + p2 * p2 + p3 * p3;
    nsq += __shfl_xor_sync(0xffffffffu, nsq, 1);
    nsq += __shfl_xor_sync(0xffffffffu, nsq, 2);
    const float nrm = sqrtf(nsq);
    const float scale = (nsq / (1.0f + nsq)) / (nrm + 1e-12f);

    ((float4*)sf)[wrp * 33 + (o * 4 + g)] =
        make_float4(p0 * scale, p1 * scale, p2 * scale, p3 * scale);
    __syncthreads();

    // out[(b*128 + oa)*32768 + pos], transposed write for coalescing
    for (int j = tid; j < 1024; j += 256) {
        const int oa = j >> 3;
        const int pp = j & 7;
        out[(size_t)(b * 128 + oa) * 32768 + posbase + pp] = sf[pp * 132 + oa];
    }
}

// ---------------- Launch ---------------------------------------------------
extern "C" void kernel_launch(void* const* d_in, const int* in_sizes, int n_in,
                              void* d_out, int out_size) {
    const float* x      = (const float*)d_in[0];
    const float* w      = (const float*)d_in[1];
    const float* cb     = (const float*)d_in[2];
    const float* biases = (const float*)d_in[3];
    float* out = (float*)d_out;

    cudaFuncSetAttribute(conv_votes_kernel,
                         cudaFuncAttributeMaxDynamicSharedMemorySize,
                         SMEM_BYTES);
    conv_votes_kernel<<<dim3(64, 16), 256, SMEM_BYTES>>>(x, w, cb);
    routing_kernel<<<8192, 256>>>(biases, out);
}